// round 1
// baseline (speedup 1.0000x reference)
#include <cuda_runtime.h>

#define LMAX  6
#define BATCH 1024
#define F     64
#define IR    455
#define NROT  64
#define FS    (F * IR)   // 29120 floats per batch element

// Packed, pre-scaled weight matrices W_l[k, n], k=(f*d+u), n=(g*d+v), row-major KxN.
// Total size = sum_l (64 d)^2 = 4096 * 455 floats = 7.45 MB.
__device__ float g_W[4096 * 455];

// d per l and irrep offsets off[l] = cumsum d^2 = {0,1,10,35,84,165,286}
// Note W offset for block l = 4096 * off[l].

// ---------------------------------------------------------------------------
// Kernel 1: W_l[(f*d+u), (g*d+v)] = scale_l * sum_r D[r, off + u*d + v] * w[f,g,r]
// scale_l = 1/(sqrt(64) * sqrt(64*d)) = 1/(64*sqrt(d))
// grid = (7, 64) -> (l, f), 256 threads.
// ---------------------------------------------------------------------------
__global__ void __launch_bounds__(256) build_w_kernel(const float* __restrict__ D,
                                                      const float* __restrict__ w)
{
    const int dtab[7] = {1, 3, 5, 7, 9, 11, 13};
    const int otab[7] = {0, 1, 10, 35, 84, 165, 286};

    const int l   = blockIdx.x;
    const int f   = blockIdx.y;
    const int d   = dtab[l];
    const int off = otab[l];
    const int d2  = d * d;
    const int N   = 64 * d;
    const int Woff = 4096 * otab[l];
    const float scale = rsqrtf((float)d) * (1.0f / 64.0f);

    __shared__ float Dsh[64 * 169];   // 43264 B, max l=6

    // Stage D[:, off:off+d2] into smem
    for (int idx = threadIdx.x; idx < 64 * d2; idx += blockDim.x) {
        int r = idx / d2;
        int j = idx - r * d2;
        Dsh[r * d2 + j] = D[r * IR + off + j];
    }
    __syncthreads();

    const float* wf = w + f * 64 * 64;   // w[f, :, :]

    for (int e = threadIdx.x; e < 64 * d2; e += blockDim.x) {
        int u   = e / (64 * d);
        int rem = e - u * 64 * d;
        int g   = rem / d;
        int v   = rem - g * d;

        const float* wr = wf + g * 64;   // w[f, g, :], contiguous over r
        const int dj = u * d + v;

        float acc = 0.0f;
#pragma unroll 8
        for (int r = 0; r < 64; ++r)
            acc += Dsh[r * d2 + dj] * wr[r];

        g_W[Woff + (f * d + u) * N + g * d + v] = scale * acc;
    }
}

// ---------------------------------------------------------------------------
// Kernel 2: per-l GEMM
//   C[(b,m), (g,v)] = sum_{(f,u)} A[(b,m),(f,u)] * W_l[(f,u),(g,v)]
//   A[(b,m),(f,u)] = x[b, f, off + u*d + m]
//   C[(b,m),(g,v)] -> out[b, g, off + v*d + m]
// M = 1024*d, N = 64*d, K = 64*d  (all exactly divisible by tile dims)
// Tile: BM=64, BN=64, BK=16, 256 threads, 4x4 per thread.
// ---------------------------------------------------------------------------
__global__ void __launch_bounds__(256) so3_gemm_kernel(const float* __restrict__ x,
                                                       float* __restrict__ out,
                                                       int d, int off, int Woff)
{
    const int N = 64 * d;
    const int K = 64 * d;

    __shared__ float As[16][64];   // As[k][row]
    __shared__ float Bs[16][64];   // Bs[k][n]

    const int t   = threadIdx.x;
    const int lr  = t & 63;        // row_local for A load / n_local for B load
    const int lc0 = t >> 6;        // 0..3 -> k_local base

    const int grow0 = blockIdx.x * 64;   // global row base
    const int gn0   = blockIdx.y * 64;   // global col base

    // A-row address decomposition (loop-invariant)
    {
        // nothing here; per-thread below
    }
    const int growA = grow0 + lr;
    const int bA = growA / d;
    const int mA = growA - bA * d;
    const float* xb = x + bA * FS + off + mA;

    const float* Wb = g_W + Woff + gn0;

    const int ty = t >> 4;   // 0..15
    const int tx = t & 15;   // 0..15

    float acc[4][4] = {};

    for (int kt = 0; kt < K; kt += 16) {
#pragma unroll
        for (int j = 0; j < 4; ++j) {
            const int kl = lc0 + j * 4;      // 0..15
            const int k  = kt + kl;
            const int f  = k / d;
            const int u  = k - f * d;
            As[kl][lr] = xb[f * IR + u * d];
            Bs[kl][lr] = Wb[k * N + lr];
        }
        __syncthreads();

#pragma unroll
        for (int kk = 0; kk < 16; ++kk) {
            float4 a4 = *(const float4*)&As[kk][ty * 4];
            float4 b4 = *(const float4*)&Bs[kk][tx * 4];
            float av[4] = {a4.x, a4.y, a4.z, a4.w};
            float bv[4] = {b4.x, b4.y, b4.z, b4.w};
#pragma unroll
            for (int i = 0; i < 4; ++i)
#pragma unroll
                for (int j = 0; j < 4; ++j)
                    acc[i][j] += av[i] * bv[j];
        }
        __syncthreads();
    }

    // Epilogue: scatter into out[b, g, off + v*d + m]
#pragma unroll
    for (int i = 0; i < 4; ++i) {
        const int grow = grow0 + ty * 4 + i;
        const int b = grow / d;
        const int m = grow - b * d;
        float* ob = out + b * FS + off + m;
#pragma unroll
        for (int j = 0; j < 4; ++j) {
            const int n = gn0 + tx * 4 + j;
            const int g = n / d;
            const int v = n - g * d;
            ob[g * IR + v * d] = acc[i][j];
        }
    }
}

// ---------------------------------------------------------------------------
extern "C" void kernel_launch(void* const* d_in, const int* in_sizes, int n_in,
                              void* d_out, int out_size)
{
    // Identify inputs by element count (robust to ordering):
    //   x: 1024*64*455 = 29,818,880 ; D: 64*455 = 29,120 ; w: 64*64*64 = 262,144
    const float* x = nullptr;
    const float* D = nullptr;
    const float* w = nullptr;
    for (int i = 0; i < n_in; ++i) {
        if (in_sizes[i] == NROT * IR)        D = (const float*)d_in[i];
        else if (in_sizes[i] == F * F * NROT) w = (const float*)d_in[i];
        else                                  x = (const float*)d_in[i];
    }
    float* out = (float*)d_out;

    // Stage 1: build packed, pre-scaled weight matrices
    build_w_kernel<<<dim3(LMAX + 1, F), 256>>>(D, w);

    // Stage 2: per-l GEMMs (stream-ordered after stage 1)
    const int dtab[7] = {1, 3, 5, 7, 9, 11, 13};
    const int otab[7] = {0, 1, 10, 35, 84, 165, 286};
    for (int l = 0; l <= LMAX; ++l) {
        const int d = dtab[l];
        dim3 grid(16 * d, d);   // M/64 = 1024*d/64 = 16d ; N/64 = d
        so3_gemm_kernel<<<grid, 256>>>(x, out, d, otab[l], 4096 * otab[l]);
    }
}

// round 4
// speedup vs baseline: 1.1349x; 1.1349x over previous
#include <cuda_runtime.h>
#include <cstdint>

#define LMAX  6
#define BATCH 1024
#define F     64
#define IR    455
#define NROT  64
#define FS    (F * IR)   // 29120 floats per batch element

// Packed, pre-scaled weight matrices W_l[k, n], k=(f*d+u), n=(g*d+v), row-major KxN.
__device__ float g_W[4096 * 455];

// ---------------------------------------------------------------------------
// Kernel 1: W_l[(f*d+u), (g*d+v)] = scale_l * sum_r D[r, off + u*d + v] * w[f,g,r]
// scale_l = 1/(64*sqrt(d)).  grid = (7, 64) -> (l, f), 256 threads.
// ---------------------------------------------------------------------------
__global__ void __launch_bounds__(256) build_w_kernel(const float* __restrict__ D,
                                                      const float* __restrict__ w)
{
    const int dtab[7] = {1, 3, 5, 7, 9, 11, 13};
    const int otab[7] = {0, 1, 10, 35, 84, 165, 286};

    const int l   = blockIdx.x;
    const int f   = blockIdx.y;
    const int d   = dtab[l];
    const int off = otab[l];
    const int d2  = d * d;
    const int N   = 64 * d;
    const int Woff = 4096 * otab[l];
    const float scale = rsqrtf((float)d) * (1.0f / 64.0f);

    __shared__ float Dsh[64 * 169];

    for (int idx = threadIdx.x; idx < 64 * d2; idx += blockDim.x) {
        int r = idx / d2;
        int j = idx - r * d2;
        Dsh[r * d2 + j] = D[r * IR + off + j];
    }
    __syncthreads();

    const float* wf = w + f * 64 * 64;

    for (int e = threadIdx.x; e < 64 * d2; e += blockDim.x) {
        int u   = e / (64 * d);
        int rem = e - u * 64 * d;
        int g   = rem / d;
        int v   = rem - g * d;

        const float* wr = wf + g * 64;
        const int dj = u * d + v;

        float acc = 0.0f;
#pragma unroll 8
        for (int r = 0; r < 64; ++r)
            acc += Dsh[r * d2 + dj] * wr[r];

        g_W[Woff + (f * d + u) * N + g * d + v] = scale * acc;
    }
}

// ---------------------------------------------------------------------------
// tf32 helpers
// ---------------------------------------------------------------------------
__device__ __forceinline__ float f2tf32(float x) {
    uint32_t r;
    asm("cvt.rna.tf32.f32 %0, %1;" : "=r"(r) : "f"(x));
    return __uint_as_float(r);
}

__device__ __forceinline__ void mma_tf32(float c[4],
                                         const uint32_t a[4],
                                         const uint32_t b[2])
{
    asm volatile(
        "mma.sync.aligned.m16n8k8.row.col.f32.tf32.tf32.f32 "
        "{%0,%1,%2,%3}, {%4,%5,%6,%7}, {%8,%9}, {%0,%1,%2,%3};"
        : "+f"(c[0]), "+f"(c[1]), "+f"(c[2]), "+f"(c[3])
        : "r"(a[0]), "r"(a[1]), "r"(a[2]), "r"(a[3]), "r"(b[0]), "r"(b[1]));
}

// ---------------------------------------------------------------------------
// Kernel 2: per-l GEMM with tf32 tensor cores, 3xTF32 split.
//   C[(b,m),(g,v)] = sum_{(f,u)} A[(b,m),(f,u)] * W_l[(f,u),(g,v)]
//   A[(b,m),(f,u)] = x[b, f, off + u*d + m]
//   C -> out[b, g, off + v*d + m]
// M = 1024*d, N = 64*d, K = 64*d
// Block tile 128x64, BK=16. 256 threads = 8 warps (4x2 of 32x32 warp tiles).
// ---------------------------------------------------------------------------
__global__ void __launch_bounds__(256) so3_mma_kernel(const float* __restrict__ x,
                                                      float* __restrict__ out,
                                                      int d, int off, int Woff)
{
    const int N = 64 * d;
    const int K = 64 * d;

    __shared__ float As_hi[16][132];
    __shared__ float As_lo[16][132];
    __shared__ float Bs_hi[16][68];
    __shared__ float Bs_lo[16][68];

    const int t    = threadIdx.x;
    const int wid  = t >> 5;
    const int lane = t & 31;
    const int g    = lane >> 2;   // 0..7
    const int tg   = lane & 3;    // 0..3
    const int wm   = (wid & 3) * 32;   // warp m-offset in block
    const int wn   = (wid >> 2) * 32;  // warp n-offset in block

    // ---- global load mapping ----
    const int lrA  = t & 127;          // A row within block tile
    const int kcA  = t >> 7;           // 0..1
    const int growA = blockIdx.x * 128 + lrA;
    const int bA = growA / d;
    const int mA = growA - bA * d;
    const float* xb = x + bA * FS + off + mA;

    const int lnB = t & 63;            // B col within block tile
    const int kcB = t >> 6;            // 0..3
    const float* Wb = g_W + Woff + blockIdx.y * 64 + lnB;

    float acc[2][4][4] = {};

    for (int kt = 0; kt < K; kt += 16) {
        // stage A (gather + tf32 split)
#pragma unroll
        for (int j = 0; j < 8; ++j) {
            const int kl = kcA + j * 2;
            const int k  = kt + kl;
            const int f  = k / d;
            const int u  = k - f * d;
            float a  = xb[f * IR + u * d];
            float ah = f2tf32(a);
            As_hi[kl][lrA] = ah;
            As_lo[kl][lrA] = f2tf32(a - ah);
        }
        // stage B (coalesced + tf32 split)
#pragma unroll
        for (int j = 0; j < 4; ++j) {
            const int kl = kcB + j * 4;
            float b  = Wb[(kt + kl) * N];
            float bh = f2tf32(b);
            Bs_hi[kl][lnB] = bh;
            Bs_lo[kl][lnB] = f2tf32(b - bh);
        }
        __syncthreads();

#pragma unroll
        for (int ks = 0; ks < 16; ks += 8) {
            uint32_t ah[2][4], al[2][4], bh[4][2], bl[4][2];
#pragma unroll
            for (int mi = 0; mi < 2; ++mi) {
                const int mb = wm + mi * 16 + g;
                ah[mi][0] = __float_as_uint(As_hi[ks + tg    ][mb    ]);
                ah[mi][1] = __float_as_uint(As_hi[ks + tg    ][mb + 8]);
                ah[mi][2] = __float_as_uint(As_hi[ks + tg + 4][mb    ]);
                ah[mi][3] = __float_as_uint(As_hi[ks + tg + 4][mb + 8]);
                al[mi][0] = __float_as_uint(As_lo[ks + tg    ][mb    ]);
                al[mi][1] = __float_as_uint(As_lo[ks + tg    ][mb + 8]);
                al[mi][2] = __float_as_uint(As_lo[ks + tg + 4][mb    ]);
                al[mi][3] = __float_as_uint(As_lo[ks + tg + 4][mb + 8]);
            }
#pragma unroll
            for (int ni = 0; ni < 4; ++ni) {
                const int nb = wn + ni * 8 + g;
                bh[ni][0] = __float_as_uint(Bs_hi[ks + tg    ][nb]);
                bh[ni][1] = __float_as_uint(Bs_hi[ks + tg + 4][nb]);
                bl[ni][0] = __float_as_uint(Bs_lo[ks + tg    ][nb]);
                bl[ni][1] = __float_as_uint(Bs_lo[ks + tg + 4][nb]);
            }
#pragma unroll
            for (int mi = 0; mi < 2; ++mi)
#pragma unroll
                for (int ni = 0; ni < 4; ++ni) {
                    mma_tf32(acc[mi][ni], ah[mi], bh[ni]);   // hi*hi
                    mma_tf32(acc[mi][ni], ah[mi], bl[ni]);   // hi*lo
                    mma_tf32(acc[mi][ni], al[mi], bh[ni]);   // lo*hi
                }
        }
        __syncthreads();
    }

    // ---- epilogue: scatter ----
#pragma unroll
    for (int mi = 0; mi < 2; ++mi) {
#pragma unroll
        for (int cr = 0; cr < 2; ++cr) {   // row half: +0 / +8
            const int row = blockIdx.x * 128 + wm + mi * 16 + g + cr * 8;
            const int b = row / d;
            const int m = row - b * d;
            float* ob = out + b * FS + off + m;
#pragma unroll
            for (int ni = 0; ni < 4; ++ni) {
#pragma unroll
                for (int cc = 0; cc < 2; ++cc) {
                    const int col = blockIdx.y * 64 + wn + ni * 8 + tg * 2 + cc;
                    const int gg = col / d;
                    const int v  = col - gg * d;
                    ob[gg * IR + v * d] = acc[mi][ni][cr * 2 + cc];
                }
            }
        }
    }
}

// ---------------------------------------------------------------------------
extern "C" void kernel_launch(void* const* d_in, const int* in_sizes, int n_in,
                              void* d_out, int out_size)
{
    const float* x = nullptr;
    const float* D = nullptr;
    const float* w = nullptr;
    for (int i = 0; i < n_in; ++i) {
        if (in_sizes[i] == NROT * IR)         D = (const float*)d_in[i];
        else if (in_sizes[i] == F * F * NROT) w = (const float*)d_in[i];
        else                                  x = (const float*)d_in[i];
    }
    float* out = (float*)d_out;

    build_w_kernel<<<dim3(LMAX + 1, F), 256>>>(D, w);

    const int dtab[7] = {1, 3, 5, 7, 9, 11, 13};
    const int otab[7] = {0, 1, 10, 35, 84, 165, 286};
    for (int l = 0; l <= LMAX; ++l) {
        const int d = dtab[l];
        dim3 grid(8 * d, d);   // M/128 = 8d ; N/64 = d
        so3_mma_kernel<<<grid, 256>>>(x, out, d, otab[l], 4096 * otab[l]);
    }
}